// round 7
// baseline (speedup 1.0000x reference)
#include <cuda_runtime.h>
#include <cstdint>

// CrossScan: x (B=16, C=96, H=128, W=128) fp32 ->
// out (B, 4, C, H*W):
//   s=0: row-major flatten (identity)
//   s=1: HW-transposed flatten
//   s=2: s=0 reversed
//   s=3: s=1 reversed
//
// Block: 32 rows (h) x 128 cols (w) of one (b,c). 256 threads, 16KB smem.
//
// Cache policy (R7): loads ld.global.L2::evict_last.v8 (pin 100.7MB input in
// 126MB L2 across graph replays); stores st.global.cs.v4 (evict-FIRST, so the
// 403MB write stream is sacrificed by L2 replacement instead of the input).
//
// Smem: tile4[32][32] float4 groups, slot = perm(g) ^ (r>>2),
// perm(g) = ((g&1)<<4)|(g>>1).
//   Phase-1 STS (thread m, groups 2m/2m+1): slots m^s and 16+(m^s);
//     per-8-lane phase low-3 bits distinct -> conflict-free.
//   Phase-2 LDS (wq fixed per phase, hi varies 0..7): slot perm(wq)^hi;
//     low-3 bits distinct -> conflict-free.

#define B_ 16
#define C_ 96
#define H_ 128
#define W_ 128
#define HW_ (H_ * W_)

__device__ __forceinline__ void ld_el8(const float* p, float4& a, float4& b) {
    unsigned u0, u1, u2, u3, u4, u5, u6, u7;
    asm volatile(
        "ld.global.L2::evict_last.v8.b32 {%0, %1, %2, %3, %4, %5, %6, %7}, [%8];"
        : "=r"(u0), "=r"(u1), "=r"(u2), "=r"(u3),
          "=r"(u4), "=r"(u5), "=r"(u6), "=r"(u7)
        : "l"(p));
    a.x = __uint_as_float(u0); a.y = __uint_as_float(u1);
    a.z = __uint_as_float(u2); a.w = __uint_as_float(u3);
    b.x = __uint_as_float(u4); b.y = __uint_as_float(u5);
    b.z = __uint_as_float(u6); b.w = __uint_as_float(u7);
}

__device__ __forceinline__ void stcs4(float* p, float4 v) {
    asm volatile("st.global.cs.v4.f32 [%0], {%1, %2, %3, %4};"
                 :: "l"(p), "f"(v.x), "f"(v.y), "f"(v.z), "f"(v.w)
                 : "memory");
}

__device__ __forceinline__ int perm(int g) {   // float4-group permutation
    return ((g & 1) << 4) | (g >> 1);
}

__global__ __launch_bounds__(256) void cross_scan_kernel(
    const float* __restrict__ x, float* __restrict__ out)
{
    __shared__ float4 tile4[32 * 32];   // 16 KB

    const int bc = blockIdx.y;          // 0 .. B*C-1
    const int b  = bc / C_;
    const int c  = bc - b * C_;
    const int h0 = blockIdx.x * 32;     // tile's first row

    const int tx = threadIdx.x;         // 0..31 (lane)
    const int ty = threadIdx.y;         // 0..7
    const int t  = ty * 32 + tx;        // 0..255

    const float* in = x + (size_t)bc * HW_;
    float* o0 = out + ((size_t)(b * 4 + 0) * C_ + c) * HW_;
    float* o1 = out + ((size_t)(b * 4 + 1) * C_ + c) * HW_;
    float* o2 = out + ((size_t)(b * 4 + 2) * C_ + c) * HW_;
    float* o3 = out + ((size_t)(b * 4 + 3) * C_ + c) * HW_;

    // ---- Phase 1: v8 load, write y0 + y2, stage smem ----
    const int m = t & 15;               // 16 threads per row
#pragma unroll
    for (int i = 0; i < 2; ++i) {
        const int r  = (t >> 4) + i * 16;      // row 0..31
        const int cb = 8 * m;                  // float col base (32B aligned)
        const int j  = (h0 + r) * W_ + cb;

        float4 a, bb;
        ld_el8(in + j, a, bb);

        // y0: identity
        stcs4(o0 + j, a);
        stcs4(o0 + j + 4, bb);

        // y2: elems j+k -> HW-1-j-k. First quad at HW-4-j, second at HW-8-j.
        stcs4(o2 + (HW_ - 4 - j), make_float4(a.w, a.z, a.y, a.x));
        stcs4(o2 + (HW_ - 8 - j), make_float4(bb.w, bb.z, bb.y, bb.x));

        // stage: groups g=2m (a), 2m+1 (b), slot = perm(g) ^ (r>>2)
        const int s = r >> 2;
        tile4[r * 32 + (m ^ s)]        = a;    // perm(2m)   = m
        tile4[r * 32 + (16 + (m ^ s))] = bb;   // perm(2m+1) = 16+m  (s<8)
    }

    __syncthreads();

    // ---- Phase 2: transposed views y1, y3 via 4x4 register transpose ----
    // Thread (tx,ty): hi = tx&7, wi = tx>>3, wq = 4*ty + wi.
    // Covers rows r = 4*hi..4*hi+3, cols w = 4*wq..4*wq+3.
    {
        const int hi = tx & 7;
        const int wi = tx >> 3;
        const int wq = 4 * ty + wi;
        const int pq = perm(wq);

        float4 r0 = tile4[(4 * hi + 0) * 32 + (pq ^ hi)];
        float4 r1 = tile4[(4 * hi + 1) * 32 + (pq ^ hi)];
        float4 r2 = tile4[(4 * hi + 2) * 32 + (pq ^ hi)];
        float4 r3 = tile4[(4 * hi + 3) * 32 + (pq ^ hi)];

        // columns: ck = x[4hi..4hi+3][4wq+k]
        float4 c0 = make_float4(r0.x, r1.x, r2.x, r3.x);
        float4 c1 = make_float4(r0.y, r1.y, r2.y, r3.y);
        float4 c2 = make_float4(r0.z, r1.z, r2.z, r3.z);
        float4 c3 = make_float4(r0.w, r1.w, r2.w, r3.w);

        const int hbase = h0 + 4 * hi;
        const int i0 = (4 * wq + 0) * H_ + hbase;
        const int i1 = (4 * wq + 1) * H_ + hbase;
        const int i2 = (4 * wq + 2) * H_ + hbase;
        const int i3 = (4 * wq + 3) * H_ + hbase;

        // y1: ascending along h, coalesced per 8-lane group
        stcs4(o1 + i0, c0);
        stcs4(o1 + i1, c1);
        stcs4(o1 + i2, c2);
        stcs4(o1 + i3, c3);

        // y3: reversed; elems i..i+3 land at HW-1-i..HW-4-i
        stcs4(o3 + (HW_ - 4 - i0), make_float4(c0.w, c0.z, c0.y, c0.x));
        stcs4(o3 + (HW_ - 4 - i1), make_float4(c1.w, c1.z, c1.y, c1.x));
        stcs4(o3 + (HW_ - 4 - i2), make_float4(c2.w, c2.z, c2.y, c2.x));
        stcs4(o3 + (HW_ - 4 - i3), make_float4(c3.w, c3.z, c3.y, c3.x));
    }
}

extern "C" void kernel_launch(void* const* d_in, const int* in_sizes, int n_in,
                              void* d_out, int out_size)
{
    const float* x = (const float*)d_in[0];
    float* out = (float*)d_out;
    (void)in_sizes; (void)n_in; (void)out_size;

    dim3 block(32, 8);
    dim3 grid(H_ / 32, B_ * C_);
    cross_scan_kernel<<<grid, block>>>(x, out);
}

// round 9
// speedup vs baseline: 1.2884x; 1.2884x over previous
#include <cuda_runtime.h>
#include <cstdint>

// CrossScan: x (B=16, C=96, H=128, W=128) fp32 ->
// out (B, 4, C, H*W):
//   s=0: row-major flatten (identity)
//   s=1: HW-transposed flatten
//   s=2: s=0 reversed
//   s=3: s=1 reversed
//
// Block: 32 rows (h) x 128 cols (w) of one (b,c). 256 threads, 16KB smem.
// Smem tile4[32][32] (float4), XOR-swizzled: slot = q ^ (r>>2).
// Phase 2 does a 4x4 register transpose so y1/y3 use STG.128.
// Stores: st.global.wt (best policy found). Loads: __ldcs.
//
// R8: grid order swapped to (bc, hq) — concurrently-resident blocks share the
// same h-quadrant across ADJACENT bc values, clustering the in-flight write
// streams into contiguous DRAM spans (better row-buffer locality) instead of
// scattering across 4 quadrants of ~300 bc regions.

#define B_ 16
#define C_ 96
#define H_ 128
#define W_ 128
#define HW_ (H_ * W_)

__device__ __forceinline__ void stwt4(float* p, float4 v) {
    asm volatile("st.global.wt.v4.f32 [%0], {%1, %2, %3, %4};"
                 :: "l"(p), "f"(v.x), "f"(v.y), "f"(v.z), "f"(v.w)
                 : "memory");
}

__global__ __launch_bounds__(256) void cross_scan_kernel(
    const float* __restrict__ x, float* __restrict__ out)
{
    __shared__ float4 tile4[32 * 32];   // 16 KB

    const int bc = blockIdx.x;          // 0 .. B*C-1  (fastest -> adjacent concurrency)
    const int b  = bc / C_;
    const int c  = bc - b * C_;
    const int h0 = blockIdx.y * 32;     // tile's first row (h-quadrant, slow axis)

    const int tx = threadIdx.x;         // 0..31 (lane)
    const int ty = threadIdx.y;         // 0..7

    const float* in = x + (size_t)bc * HW_;
    float* o0 = out + ((size_t)(b * 4 + 0) * C_ + c) * HW_;
    float* o1 = out + ((size_t)(b * 4 + 1) * C_ + c) * HW_;
    float* o2 = out + ((size_t)(b * 4 + 2) * C_ + c) * HW_;
    float* o3 = out + ((size_t)(b * 4 + 3) * C_ + c) * HW_;

    // ---- Phase 1: load tile, write y0 (identity) + y2 (reversed), stage smem ----
    const int wb = tx * 4;              // float column base
#pragma unroll
    for (int i = 0; i < 4; ++i) {
        const int r = ty + i * 8;       // row within tile (0..31)
        const int j = (h0 + r) * W_ + wb;

        float4 v = __ldcs(reinterpret_cast<const float4*>(in + j));

        // y0: identity, coalesced
        stwt4(o0 + j, v);

        // y2: elems j..j+3 land at HW-1-j..HW-4-j -> reversed float4 at HW-4-j
        float4 rv = make_float4(v.w, v.z, v.y, v.x);
        stwt4(o2 + (HW_ - 4 - j), rv);

        tile4[r * 32 + (tx ^ (r >> 2))] = v;
    }

    __syncthreads();

    // ---- Phase 2: transposed views y1, y3 via 4x4 register transpose ----
    // Thread (tx,ty): hi = tx&7, wi = tx>>3, wq = 4*ty + wi.
    // Covers rows r = 4*hi..4*hi+3, cols w = 4*wq..4*wq+3.
    {
        const int hi = tx & 7;
        const int wi = tx >> 3;
        const int wq = 4 * ty + wi;

        float4 r0 = tile4[(4 * hi + 0) * 32 + (wq ^ hi)];
        float4 r1 = tile4[(4 * hi + 1) * 32 + (wq ^ hi)];
        float4 r2 = tile4[(4 * hi + 2) * 32 + (wq ^ hi)];
        float4 r3 = tile4[(4 * hi + 3) * 32 + (wq ^ hi)];

        // columns: ck = x[4hi..4hi+3][4wq+k]
        float4 c0 = make_float4(r0.x, r1.x, r2.x, r3.x);
        float4 c1 = make_float4(r0.y, r1.y, r2.y, r3.y);
        float4 c2 = make_float4(r0.z, r1.z, r2.z, r3.z);
        float4 c3 = make_float4(r0.w, r1.w, r2.w, r3.w);

        const int hbase = h0 + 4 * hi;
        const int i0 = (4 * wq + 0) * H_ + hbase;
        const int i1 = (4 * wq + 1) * H_ + hbase;
        const int i2 = (4 * wq + 2) * H_ + hbase;
        const int i3 = (4 * wq + 3) * H_ + hbase;

        // y1: ascending along h, 128B per 8-lane group, coalesced
        stwt4(o1 + i0, c0);
        stwt4(o1 + i1, c1);
        stwt4(o1 + i2, c2);
        stwt4(o1 + i3, c3);

        // y3: reversed; elems i..i+3 land at HW-1-i..HW-4-i -> reversed float4
        stwt4(o3 + (HW_ - 4 - i0), make_float4(c0.w, c0.z, c0.y, c0.x));
        stwt4(o3 + (HW_ - 4 - i1), make_float4(c1.w, c1.z, c1.y, c1.x));
        stwt4(o3 + (HW_ - 4 - i2), make_float4(c2.w, c2.z, c2.y, c2.x));
        stwt4(o3 + (HW_ - 4 - i3), make_float4(c3.w, c3.z, c3.y, c3.x));
    }
}

extern "C" void kernel_launch(void* const* d_in, const int* in_sizes, int n_in,
                              void* d_out, int out_size)
{
    const float* x = (const float*)d_in[0];
    float* out = (float*)d_out;
    (void)in_sizes; (void)n_in; (void)out_size;

    dim3 block(32, 8);
    dim3 grid(B_ * C_, H_ / 32);
    cross_scan_kernel<<<grid, block>>>(x, out);
}

// round 10
// speedup vs baseline: 1.4002x; 1.0867x over previous
#include <cuda_runtime.h>
#include <cstdint>

// CrossScan: x (B=16, C=96, H=128, W=128) fp32 ->
// out (B, 4, C, H*W):
//   s=0: row-major flatten (identity)
//   s=1: HW-transposed flatten
//   s=2: s=0 reversed
//   s=3: s=1 reversed
//
// R9: tile = 32 h x 64 w (half of R4's) -> 12288 blocks, ~halved per-block
// latency -> shorter end-of-kernel drain where DRAM demand ramps down.
// 256 threads, 8KB smem. Loads __ldcs, stores st.global.wt (best policy).
// Launch order: tile index fastest within bc (R4's proven order).
//
// Smem tile4[32][16] float4, slot = (q&8) | ((q&7) ^ s), s = (r>>1)&7.
//   Phase-1 STS: 8-lane phase has r fixed, q distinct mod 8 -> conflict-free.
//   Phase-2 LDS: 8-lane phase has wq fixed, s = hi&7 distinct -> conflict-free.

#define B_ 16
#define C_ 96
#define H_ 128
#define W_ 128
#define HW_ (H_ * W_)

__device__ __forceinline__ void stwt4(float* p, float4 v) {
    asm volatile("st.global.wt.v4.f32 [%0], {%1, %2, %3, %4};"
                 :: "l"(p), "f"(v.x), "f"(v.y), "f"(v.z), "f"(v.w)
                 : "memory");
}

__device__ __forceinline__ void stwt2(float* p, float a, float b) {
    asm volatile("st.global.wt.v2.f32 [%0], {%1, %2};"
                 :: "l"(p), "f"(a), "f"(b)
                 : "memory");
}

__global__ __launch_bounds__(256) void cross_scan_kernel(
    const float* __restrict__ x, float* __restrict__ out)
{
    __shared__ float4 tile4[32 * 16];   // 8 KB

    const int bc = blockIdx.y;          // 0 .. B*C-1 (slow axis, as in R4)
    const int b  = bc / C_;
    const int c  = bc - b * C_;
    const int h0 = (blockIdx.x >> 1) * 32;   // h-quadrant
    const int w0 = (blockIdx.x & 1) * 64;    // w-half

    const int t  = threadIdx.x;         // 0..255
    const int tx = t & 31;              // lane
    const int ty = t >> 5;              // warp 0..7

    const float* in = x + (size_t)bc * HW_;
    float* o0 = out + ((size_t)(b * 4 + 0) * C_ + c) * HW_;
    float* o1 = out + ((size_t)(b * 4 + 1) * C_ + c) * HW_;
    float* o2 = out + ((size_t)(b * 4 + 2) * C_ + c) * HW_;
    float* o3 = out + ((size_t)(b * 4 + 3) * C_ + c) * HW_;

    // ---- Phase 1: load tile (32x64), write y0 + y2, stage smem ----
    const int m     = t & 15;           // col group (float4) 0..15
    const int rbase = t >> 4;           // 0..15
#pragma unroll
    for (int i = 0; i < 2; ++i) {
        const int r = rbase + i * 16;   // row within tile 0..31
        const int j = (h0 + r) * W_ + w0 + 4 * m;

        float4 v = __ldcs(reinterpret_cast<const float4*>(in + j));

        // y0: identity; warp covers 2 rows x 256B, coalesced
        stwt4(o0 + j, v);

        // y2: elems j..j+3 -> HW-1-j..HW-4-j; reversed float4 at HW-4-j
        stwt4(o2 + (HW_ - 4 - j), make_float4(v.w, v.z, v.y, v.x));

        // stage: slot = (m&8) | ((m&7) ^ s), s = (r>>1)&7
        const int s = (r >> 1) & 7;
        tile4[r * 16 + ((m & 8) | ((m & 7) ^ s))] = v;
    }

    __syncthreads();

    // ---- Phase 2: transposed views y1, y3 via 2x4 register transpose ----
    // Thread: hi = tx&15 (rows 2hi, 2hi+1), wq = 2*ty + (tx>>4) (cols 4wq..4wq+3).
    {
        const int hi = tx & 15;
        const int u  = tx >> 4;
        const int wq = 2 * ty + u;      // 0..15
        const int s  = hi & 7;          // (rA>>1)&7 for rA = 2hi
        const int slot = (wq & 8) | ((wq & 7) ^ s);

        float4 ra = tile4[(2 * hi + 0) * 16 + slot];
        float4 rb = tile4[(2 * hi + 1) * 16 + slot];

        const int hbase = h0 + 2 * hi;
        const int cg = w0 + 4 * wq;     // global w of component 0

        const int i0 = (cg + 0) * H_ + hbase;
        const int i1 = (cg + 1) * H_ + hbase;
        const int i2 = (cg + 2) * H_ + hbase;
        const int i3 = (cg + 3) * H_ + hbase;

        // y1: per w-column, 16 lanes x float2 = 128B ascending h, coalesced
        stwt2(o1 + i0, ra.x, rb.x);
        stwt2(o1 + i1, ra.y, rb.y);
        stwt2(o1 + i2, ra.z, rb.z);
        stwt2(o1 + i3, ra.w, rb.w);

        // y3: elems i, i+1 -> HW-1-i, HW-2-i; reversed float2 at HW-2-i
        stwt2(o3 + (HW_ - 2 - i0), rb.x, ra.x);
        stwt2(o3 + (HW_ - 2 - i1), rb.y, ra.y);
        stwt2(o3 + (HW_ - 2 - i2), rb.z, ra.z);
        stwt2(o3 + (HW_ - 2 - i3), rb.w, ra.w);
    }
}

extern "C" void kernel_launch(void* const* d_in, const int* in_sizes, int n_in,
                              void* d_out, int out_size)
{
    const float* x = (const float*)d_in[0];
    float* out = (float*)d_out;
    (void)in_sizes; (void)n_in; (void)out_size;

    dim3 block(256);
    dim3 grid((H_ / 32) * (W_ / 64), B_ * C_);   // 8 x 1536
    cross_scan_kernel<<<grid, block>>>(x, out);
}